// round 4
// baseline (speedup 1.0000x reference)
#include <cuda_runtime.h>
#include <math.h>

#define Bc 4
#define Sc 64
#define Dc 512
#define Hc 8
#define DHc 64
#define DFFc 2048
#define Lc 2
#define Vc 32128
#define Tc 16
#define NEGB (-1e9f)

// ---- scratch layout (floats) in one __device__ buffer (no allocations) ----
#define O_X      0          // 256*512 encoder residual
#define O_H      131072     // 256*512 normed
#define O_Q      262144
#define O_K      393216
#define O_V      524288
#define O_ATTN   655360
#define O_HS     786432     // encoder output
#define O_FF     917504     // 256*2048
#define O_ENCK   1441792    // 2*256*512 cross K per layer
#define O_ENCV   1703936    // 2*256*512 cross V per layer
#define O_DX     1966080    // 4*512 decoder residual / next-token emb
#define O_DQ     1968128    // 4*512
#define O_DATTN  1970176    // 4*512
#define O_DFF    1972224    // 4*2048
#define O_SK     1980416    // 2*4*16*512 self K cache
#define O_SV     2045952    // 2*4*16*512 self V cache
#define O_LOGITS 2111488    // 4*32128
#define O_PP     2240000    // 64 * 4 * 512 split-K partials
#define SCRATCH  2371072

__device__ float g_s[SCRATCH];

// ---------------- embedding ----------------
__global__ void k_embed(const int* __restrict__ ids, const float* __restrict__ emb) {
    int r = blockIdx.x;
    const float* s = emb + (long)ids[r] * Dc;
    float* d = g_s + O_X + (long)r * Dc;
    for (int c = threadIdx.x; c < Dc; c += blockDim.x) d[c] = s[c];
}

__global__ void k_init_dx(const float* __restrict__ emb) {
    // decoder starts from pad-token (id 0) embedding for every batch row
    g_s[O_DX + blockIdx.x * Dc + threadIdx.x] = emb[threadIdx.x];
}

// ---------------- rmsnorm over rows (encoder-side) ----------------
__global__ void k_rmsnorm(int o_in, const float* __restrict__ w, int o_out) {
    int row = blockIdx.x, tid = threadIdx.x;
    const float* x = g_s + o_in + (long)row * Dc;
    float* o = g_s + o_out + (long)row * Dc;
    float ss = 0.f;
    for (int c = tid; c < Dc; c += 128) { float v = x[c]; ss += v * v; }
    __shared__ float sw[4];
    for (int k = 16; k; k >>= 1) ss += __shfl_xor_sync(0xffffffffu, ss, k);
    if ((tid & 31) == 0) sw[tid >> 5] = ss;
    __syncthreads();
    float tot = sw[0] + sw[1] + sw[2] + sw[3];
    float inv = rsqrtf(tot * (1.0f / Dc) + 1e-6f);
    for (int c = tid; c < Dc; c += 128) o[c] = x[c] * inv * w[c];
}

// ---------------- tiled GEMM: C[M,N] = A[M,K] @ W[K,N]  (flags: 1=relu, 2=+residual) ----------------
__global__ void k_gemm(int o_a, const float* __restrict__ W, int o_c,
                       int M, int K, int N, int flags, int o_res) {
    __shared__ float As[16][64];
    __shared__ float Bs[16][64];
    int mt = blockIdx.y * 64, nt = blockIdx.x * 64;
    const float* A = g_s + o_a;
    int tid = threadIdx.x;
    float acc[4][4];
#pragma unroll
    for (int i = 0; i < 4; i++)
#pragma unroll
        for (int j = 0; j < 4; j++) acc[i][j] = 0.f;

    int ty = (tid >> 4) << 2, tx = (tid & 15) << 2;
    for (int k0 = 0; k0 < K; k0 += 16) {
        for (int i = tid; i < 64 * 16; i += 256) {
            int m = i >> 4, kk = i & 15;
            As[kk][m] = A[(long)(mt + m) * K + k0 + kk];
        }
        for (int i = tid; i < 16 * 64; i += 256) {
            int kk = i >> 6, n = i & 63;
            Bs[kk][n] = W[(long)(k0 + kk) * N + nt + n];
        }
        __syncthreads();
#pragma unroll
        for (int kk = 0; kk < 16; kk++) {
            float a[4], b[4];
#pragma unroll
            for (int i = 0; i < 4; i++) { a[i] = As[kk][ty + i]; b[i] = Bs[kk][tx + i]; }
#pragma unroll
            for (int i = 0; i < 4; i++)
#pragma unroll
                for (int j = 0; j < 4; j++) acc[i][j] += a[i] * b[j];
        }
        __syncthreads();
    }
#pragma unroll
    for (int i = 0; i < 4; i++)
#pragma unroll
        for (int j = 0; j < 4; j++) {
            int m = mt + ty + i, n = nt + tx + j;
            float v = acc[i][j];
            if (flags & 2) v += g_s[o_res + (long)m * N + n];
            if (flags & 1) v = fmaxf(v, 0.f);
            g_s[o_c + (long)m * N + n] = v;
        }
}

// ---------------- encoder attention: one block per (b,h), 64x64 ----------------
__global__ void k_enc_attn(const float* __restrict__ mask) {
    __shared__ float Qs[64][64];   // reused as P after scores
    __shared__ float Ks[64][64];
    __shared__ float Vs[64][64];
    int b = blockIdx.x >> 3, h = blockIdx.x & 7;
    int tid = threadIdx.x;
    for (int i = tid; i < 4096; i += 256) {
        int t = i >> 6, d = i & 63;
        long base = (long)(b * 64 + t) * Dc + h * 64 + d;
        Qs[t][d] = g_s[O_Q + base];
        Ks[t][d] = g_s[O_K + base];
        Vs[t][d] = g_s[O_V + base];
    }
    __syncthreads();
    // thread covers row q = tid/4, columns j = (tid%4)*16 .. +15
    int q = tid >> 2, j0 = (tid & 3) << 4;
    float sc[16];
#pragma unroll
    for (int i = 0; i < 16; i++) {
        int j = j0 + i;
        float s = 0.f;
#pragma unroll
        for (int d = 0; d < 64; d++) s += Qs[q][d] * Ks[j][d];
        s = s * 0.125f + (1.0f - mask[b * Sc + j]) * NEGB;
        sc[i] = s;
    }
    float mx = -3.4e38f;
#pragma unroll
    for (int i = 0; i < 16; i++) mx = fmaxf(mx, sc[i]);
    mx = fmaxf(mx, __shfl_xor_sync(0xffffffffu, mx, 1));
    mx = fmaxf(mx, __shfl_xor_sync(0xffffffffu, mx, 2));
    float sum = 0.f;
#pragma unroll
    for (int i = 0; i < 16; i++) { sc[i] = expf(sc[i] - mx); sum += sc[i]; }
    sum += __shfl_xor_sync(0xffffffffu, sum, 1);
    sum += __shfl_xor_sync(0xffffffffu, sum, 2);
    float inv = 1.0f / sum;
    __syncthreads();   // done reading Qs
#pragma unroll
    for (int i = 0; i < 16; i++) Qs[q][j0 + i] = sc[i] * inv;  // P
    __syncthreads();
    // output: out[q][d] = sum_j P[q][j] * V[j][d]
    int oq = tid >> 2, d0 = (tid & 3) << 4;
#pragma unroll
    for (int i = 0; i < 16; i++) {
        int d = d0 + i;
        float o = 0.f;
#pragma unroll
        for (int j = 0; j < 64; j++) o += Qs[oq][j] * Vs[j][d];
        g_s[O_ATTN + (long)(b * 64 + oq) * Dc + h * 64 + d] = o;
    }
}

// ---------------- decoder fused rmsnorm + up-to-3 GEMVs (M=4, K=512) ----------------
// grid: (N/64, nmats), 256 threads. Each block: redundant norm of x[4,512] then a 64-col GEMV chunk.
__global__ void k_ln_gemv(int o_x, const float* __restrict__ lnw,
                          const float* __restrict__ W0, const float* __restrict__ W1,
                          const float* __restrict__ W2,
                          int o0, int o1, int o2, int os0, int os1, int os2,
                          int N, int relu) {
    __shared__ float xn[4][512];
    __shared__ float red[4][4][64];
    __shared__ float inv[4];
    int tid = threadIdx.x;
    for (int i = tid; i < 2048; i += 256) xn[i >> 9][i & 511] = g_s[o_x + i];
    __syncthreads();
    if (tid < 128) {
        int r = tid >> 5, lane = tid & 31;
        float ss = 0.f;
        for (int c = lane; c < 512; c += 32) { float v = xn[r][c]; ss += v * v; }
        for (int k = 16; k; k >>= 1) ss += __shfl_xor_sync(0xffffffffu, ss, k);
        if (lane == 0) inv[r] = rsqrtf(ss * (1.0f / 512.0f) + 1e-6f);
    }
    __syncthreads();
    for (int i = tid; i < 2048; i += 256) {
        int r = i >> 9, c = i & 511;
        xn[r][c] *= inv[r] * lnw[c];
    }
    __syncthreads();
    const float* W = (blockIdx.y == 0) ? W0 : ((blockIdx.y == 1) ? W1 : W2);
    int oo = (blockIdx.y == 0) ? o0 : ((blockIdx.y == 1) ? o1 : o2);
    int os = (blockIdx.y == 0) ? os0 : ((blockIdx.y == 1) ? os1 : os2);
    int col = blockIdx.x * 64 + (tid & 63);
    int ks = tid >> 6;
    float a0 = 0.f, a1 = 0.f, a2 = 0.f, a3 = 0.f;
    const float* Wp = W + col;
#pragma unroll 8
    for (int k = ks * 128; k < ks * 128 + 128; k++) {
        float w = Wp[(long)k * N];
        a0 += xn[0][k] * w; a1 += xn[1][k] * w; a2 += xn[2][k] * w; a3 += xn[3][k] * w;
    }
    int cl = tid & 63;
    red[ks][0][cl] = a0; red[ks][1][cl] = a1; red[ks][2][cl] = a2; red[ks][3][cl] = a3;
    __syncthreads();
    if (tid < 64) {
#pragma unroll
        for (int r = 0; r < 4; r++) {
            float s = red[0][r][tid] + red[1][r][tid] + red[2][r][tid] + red[3][r][tid];
            if (relu) s = fmaxf(s, 0.f);
            g_s[oo + (long)r * os + blockIdx.x * 64 + tid] = s;
        }
    }
}

// ---------------- plain GEMV (M=4, N=512, K param), optional residual ----------------
__global__ void k_gemv4(int o_x, const float* __restrict__ W, int o_out,
                        int K, int res, int o_res) {
    __shared__ float xs[4 * 2048];
    __shared__ float red[4][4][64];
    int tid = threadIdx.x;
    for (int i = tid; i < 4 * K; i += 256) xs[i] = g_s[o_x + i];
    __syncthreads();
    int col = blockIdx.x * 64 + (tid & 63);
    int ks = tid >> 6, kc = K >> 2;
    float a0 = 0.f, a1 = 0.f, a2 = 0.f, a3 = 0.f;
    const float* Wp = W + col;
#pragma unroll 8
    for (int k = ks * kc; k < ks * kc + kc; k++) {
        float w = Wp[(long)k * 512];
        a0 += xs[k] * w; a1 += xs[K + k] * w; a2 += xs[2 * K + k] * w; a3 += xs[3 * K + k] * w;
    }
    int cl = tid & 63;
    red[ks][0][cl] = a0; red[ks][1][cl] = a1; red[ks][2][cl] = a2; red[ks][3][cl] = a3;
    __syncthreads();
    if (tid < 64) {
#pragma unroll
        for (int r = 0; r < 4; r++) {
            float s = red[0][r][tid] + red[1][r][tid] + red[2][r][tid] + red[3][r][tid];
            int idx = o_out + r * 512 + blockIdx.x * 64 + tid;
            if (res) s += g_s[o_res + r * 512 + blockIdx.x * 64 + tid];
            g_s[idx] = s;
        }
    }
}

// ---------------- single-token attention step (self via cache, or cross via encK/V) ----------------
// grid = 32 (b*8+h), 64 threads
__global__ void k_attn_step(int o_q, int o_kc, int o_vc, int bstride, int count,
                            const float* __restrict__ mask, int o_out) {
    __shared__ float p[64];
    int b = blockIdx.x >> 3, h = blockIdx.x & 7;
    int j = threadIdx.x;
    const float* Kcache = g_s + o_kc + (long)b * bstride;
    const float* Vcache = g_s + o_vc + (long)b * bstride;
    const float* q = g_s + o_q + b * 512 + h * 64;
    if (j < count) {
        float s = 0.f;
#pragma unroll 8
        for (int d = 0; d < 64; d++) s += q[d] * Kcache[(long)j * 512 + h * 64 + d];
        s *= 0.125f;
        if (mask) s += (1.0f - mask[b * Sc + j]) * NEGB;
        p[j] = s;
    }
    __syncthreads();
    float mx = -3.4e38f;
    for (int jj = 0; jj < count; jj++) mx = fmaxf(mx, p[jj]);
    float sum = 0.f;
    for (int jj = 0; jj < count; jj++) sum += expf(p[jj] - mx);
    float pv = 0.f;
    if (j < count) pv = expf(p[j] - mx) / sum;
    __syncthreads();
    if (j < count) p[j] = pv;
    __syncthreads();
    int d = threadIdx.x;
    float o = 0.f;
    for (int jj = 0; jj < count; jj++) o += p[jj] * Vcache[(long)jj * 512 + h * 64 + d];
    g_s[o_out + b * 512 + h * 64 + d] = o;
}

// ---------------- softmax + argmax over V, write probs + pad flag to output ----------------
__global__ void k_softmax_out(float* __restrict__ out, int iter) {
    int b = blockIdx.x, tid = threadIdx.x;   // 512 threads
    const float* lg = g_s + O_LOGITS + (long)b * Vc;
    __shared__ float smx[512];
    __shared__ int sarg[512];
    float mx = -3.4e38f; int arg = 0;
    for (int v = tid; v < Vc; v += 512) {
        float x = lg[v];
        if (x > mx) { mx = x; arg = v; }
    }
    smx[tid] = mx; sarg[tid] = arg;
    __syncthreads();
    for (int s = 256; s; s >>= 1) {
        if (tid < s) {
            if (smx[tid + s] > smx[tid] ||
                (smx[tid + s] == smx[tid] && sarg[tid + s] < sarg[tid])) {
                smx[tid] = smx[tid + s]; sarg[tid] = sarg[tid + s];
            }
        }
        __syncthreads();
    }
    mx = smx[0];
    int amax = sarg[0];
    float sum = 0.f;
    for (int v = tid; v < Vc; v += 512) sum += expf(lg[v] - mx);
    __syncthreads();
    smx[tid] = sum;
    __syncthreads();
    for (int s = 256; s; s >>= 1) {
        if (tid < s) smx[tid] += smx[tid + s];
        __syncthreads();
    }
    float inv = 1.0f / smx[0];
    float* po = out + ((long)b * Tc + iter) * Vc;
    for (int v = tid; v < Vc; v += 512) po[v] = expf(lg[v] - mx) * inv;
    if (tid == 0) out[(long)Bc * Tc * Vc + b * Tc + iter] = (amax == 0) ? 1.0f : 0.0f;
}

// ---------------- probs @ emb : split-K partials (deterministic, no atomics) ----------------
// grid (4, 64): x = 128-col block, y = V split (502 rows each). 128 threads.
__global__ void k_pemb_partial(const float* __restrict__ out, const float* __restrict__ emb, int iter) {
    __shared__ float ps[4 * 502];
    int cb = blockIdx.x, sp = blockIdx.y, tid = threadIdx.x;
    int vs = sp * 502;
    for (int i = tid; i < 4 * 502; i += 128) {
        int r = i / 502, vv = i % 502;
        ps[i] = out[((long)r * Tc + iter) * Vc + vs + vv];
    }
    __syncthreads();
    int col = cb * 128 + tid;
    float a0 = 0.f, a1 = 0.f, a2 = 0.f, a3 = 0.f;
#pragma unroll 4
    for (int v = 0; v < 502; v++) {
        float e = emb[(long)(vs + v) * Dc + col];
        a0 += ps[v] * e; a1 += ps[502 + v] * e; a2 += ps[1004 + v] * e; a3 += ps[1506 + v] * e;
    }
    float* pp = g_s + O_PP + (long)sp * 2048 + col;
    pp[0] = a0; pp[512] = a1; pp[1024] = a2; pp[1536] = a3;
}

__global__ void k_pemb_reduce() {
    int idx = blockIdx.x * 256 + threadIdx.x;  // 0..2047
    float s = 0.f;
    for (int sp = 0; sp < 64; sp++) s += g_s[O_PP + sp * 2048 + idx];
    g_s[O_DX + idx] = s;   // next-iteration token embedding (residual-stream input)
}

// ---------------- host orchestration ----------------
extern "C" void kernel_launch(void* const* d_in, const int* in_sizes, int n_in,
                              void* d_out, int out_size) {
    (void)in_sizes; (void)n_in; (void)out_size;
    const int*   ids     = (const int*)d_in[0];
    const float* mask    = (const float*)d_in[1];
    const float* emb     = (const float*)d_in[2];
    const float* enc_wq  = (const float*)d_in[3];
    const float* enc_wk  = (const float*)d_in[4];
    const float* enc_wv  = (const float*)d_in[5];
    const float* enc_wo  = (const float*)d_in[6];
    const float* enc_ln1 = (const float*)d_in[7];
    const float* enc_w1  = (const float*)d_in[8];
    const float* enc_w2  = (const float*)d_in[9];
    const float* enc_ln2 = (const float*)d_in[10];
    const float* enc_lnf = (const float*)d_in[11];
    const float* dec_sq  = (const float*)d_in[12];
    const float* dec_sk  = (const float*)d_in[13];
    const float* dec_sv  = (const float*)d_in[14];
    const float* dec_so  = (const float*)d_in[15];
    const float* dec_ln1 = (const float*)d_in[16];
    const float* dec_cq  = (const float*)d_in[17];
    const float* dec_ck  = (const float*)d_in[18];
    const float* dec_cv  = (const float*)d_in[19];
    const float* dec_co  = (const float*)d_in[20];
    const float* dec_ln2 = (const float*)d_in[21];
    const float* dec_w1  = (const float*)d_in[22];
    const float* dec_w2  = (const float*)d_in[23];
    const float* dec_ln3 = (const float*)d_in[24];
    const float* dec_lnf = (const float*)d_in[25];
    const float* lm_head = (const float*)d_in[26];
    float* out = (float*)d_out;

    const int DD = Dc * Dc;            // 262144
    const int DF = Dc * DFFc;          // 1048576

    // ===== encoder =====
    k_embed<<<256, 128>>>(ids, emb);
    for (int l = 0; l < Lc; l++) {
        k_rmsnorm<<<256, 128>>>(O_X, enc_ln1 + l * Dc, O_H);
        k_gemm<<<dim3(8, 4), 256>>>(O_H, enc_wq + l * DD, O_Q, 256, 512, 512, 0, 0);
        k_gemm<<<dim3(8, 4), 256>>>(O_H, enc_wk + l * DD, O_K, 256, 512, 512, 0, 0);
        k_gemm<<<dim3(8, 4), 256>>>(O_H, enc_wv + l * DD, O_V, 256, 512, 512, 0, 0);
        k_enc_attn<<<32, 256>>>(mask);
        k_gemm<<<dim3(8, 4), 256>>>(O_ATTN, enc_wo + l * DD, O_X, 256, 512, 512, 2, O_X);
        k_rmsnorm<<<256, 128>>>(O_X, enc_ln2 + l * Dc, O_H);
        k_gemm<<<dim3(32, 4), 256>>>(O_H, enc_w1 + l * DF, O_FF, 256, 512, 2048, 1, 0);
        k_gemm<<<dim3(8, 4), 256>>>(O_FF, enc_w2 + l * DF, O_X, 256, 2048, 512, 2, O_X);
    }
    k_rmsnorm<<<256, 128>>>(O_X, enc_lnf, O_HS);
    // precompute cross-attention K/V per decoder layer (hs is fixed)
    for (int l = 0; l < Lc; l++) {
        k_gemm<<<dim3(8, 4), 256>>>(O_HS, dec_ck + l * DD, O_ENCK + l * 131072, 256, 512, 512, 0, 0);
        k_gemm<<<dim3(8, 4), 256>>>(O_HS, dec_cv + l * DD, O_ENCV + l * 131072, 256, 512, 512, 0, 0);
    }

    // ===== decode loop (KV-cached, math-identical to full re-run w/ causal mask) =====
    k_init_dx<<<4, 512>>>(emb);
    for (int t = 0; t < Tc; t++) {
        for (int l = 0; l < Lc; l++) {
            // ln1 + q,k,v ; k/v written straight into cache at position t
            k_ln_gemv<<<dim3(8, 3), 256>>>(O_DX, dec_ln1 + l * Dc,
                dec_sq + l * DD, dec_sk + l * DD, dec_sv + l * DD,
                O_DQ, O_SK + l * 32768 + t * 512, O_SV + l * 32768 + t * 512,
                512, 8192, 8192, 512, 0);
            k_attn_step<<<32, 64>>>(O_DQ, O_SK + l * 32768, O_SV + l * 32768,
                                    8192, t + 1, nullptr, O_DATTN);
            k_gemv4<<<8, 256>>>(O_DATTN, dec_so + l * DD, O_DX, 512, 1, O_DX);
            // ln2 + cross q
            k_ln_gemv<<<dim3(8, 1), 256>>>(O_DX, dec_ln2 + l * Dc,
                dec_cq + l * DD, dec_cq + l * DD, dec_cq + l * DD,
                O_DQ, O_DQ, O_DQ, 512, 512, 512, 512, 0);
            k_attn_step<<<32, 64>>>(O_DQ, O_ENCK + l * 131072, O_ENCV + l * 131072,
                                    32768, 64, mask, O_DATTN);
            k_gemv4<<<8, 256>>>(O_DATTN, dec_co + l * DD, O_DX, 512, 1, O_DX);
            // ln3 + FFN
            k_ln_gemv<<<dim3(32, 1), 256>>>(O_DX, dec_ln3 + l * Dc,
                dec_w1 + l * DF, dec_w1 + l * DF, dec_w1 + l * DF,
                O_DFF, O_DFF, O_DFF, 2048, 2048, 2048, 2048, 1);
            k_gemv4<<<8, 256>>>(O_DFF, dec_w2 + l * DF, O_DX, 2048, 1, O_DX);
        }
        // final rmsnorm fused into lm_head GEMV
        k_ln_gemv<<<dim3(502, 1), 256>>>(O_DX, dec_lnf,
            lm_head, lm_head, lm_head,
            O_LOGITS, O_LOGITS, O_LOGITS, Vc, Vc, Vc, Vc, 0);
        k_softmax_out<<<4, 512>>>(out, t);
        k_pemb_partial<<<dim3(4, 64), 128>>>(out, emb, t);
        k_pemb_reduce<<<8, 256>>>();
    }
}

// round 8
// speedup vs baseline: 1.1834x; 1.1834x over previous
#include <cuda_runtime.h>
#include <math.h>

#define NBMAX 128
#define NT 256
#define Dc 512
#define Hc 8
#define DFFc 2048
#define Lc 2
#define Vc 32128
#define Tc 16
#define Bc 4
#define Sc 64
#define NEGB (-1e9f)

#define DD (512*512)
#define DF (512*2048)

// ---- scratch layout (floats) ----
#define O_X      0
#define O_H      131072
#define O_Q      262144
#define O_K      393216
#define O_V      524288
#define O_ATTN   655360
#define O_HS     786432
#define O_FF     917504
#define O_ENCK   1441792
#define O_ENCV   1703936
#define O_DX     1966080
#define O_DQ     1968128
#define O_DATTN  1970176
#define O_DFF    1972224
#define O_SK     1980416
#define O_SV     2045952
#define O_LOGITS 2111488
#define O_SMAX   2240000
#define O_SARG   2240128
#define O_SSUM   2240256
#define SCRATCH  2240512

__device__ float g_s[SCRATCH];
__device__ unsigned g_cnt = 0;
__device__ unsigned g_gen = 0;

// ---- software grid barrier; nb = actual resident grid size ----
__device__ __forceinline__ void gsync(unsigned nb) {
    __syncthreads();
    if (threadIdx.x == 0) {
        __threadfence();
        unsigned gen = atomicAdd(&g_gen, 0u);      // atomic read
        if (atomicAdd(&g_cnt, 1u) == nb - 1u) {
            atomicExch(&g_cnt, 0u);
            __threadfence();
            atomicAdd(&g_gen, 1u);                 // release
        } else {
            while (atomicAdd(&g_gen, 0u) == gen) __nanosleep(128);
        }
        __threadfence();
    }
    __syncthreads();
}

struct P {
    const int* ids; const float* mask; const float* emb;
    const float *ewq, *ewk, *ewv, *ewo, *eln1, *ew1, *ew2, *eln2, *elnf;
    const float *dsq, *dsk, *dsv, *dso, *dln1;
    const float *dcq, *dck, *dcv, *dco, *dln2;
    const float *dw1, *dw2, *dln3, *dlnf, *lm;
    float* out;
};

// ---- rmsnorm over 256 rows: units = 128 pairs, 1 warp per row ----
__device__ void d_rmsnorm(int o_in, const float* __restrict__ w, int o_out, int nb) {
    int wid = threadIdx.x >> 5, lane = threadIdx.x & 31;
    for (int u = blockIdx.x; u < 128; u += nb) {
        if (wid < 2) {
            int row = u * 2 + wid;
            const float* x = g_s + o_in + row * Dc;
            float ss = 0.f;
#pragma unroll
            for (int i = 0; i < 16; i++) { float v = x[lane + 32 * i]; ss += v * v; }
#pragma unroll
            for (int k = 16; k; k >>= 1) ss += __shfl_xor_sync(0xffffffffu, ss, k);
            float inv = rsqrtf(ss * (1.0f / Dc) + 1e-6f);
            float* o = g_s + o_out + row * Dc;
#pragma unroll
            for (int i = 0; i < 16; i++) { int c = lane + 32 * i; o[c] = x[c] * inv * w[c]; }
        }
    }
}

// ---- GEMM: up to 3 matrices, M=256, tile 64x64, k-chunk 32 ----
__device__ void d_gemm3(int o_a, const float* W0, const float* W1, const float* W2,
                        int o0, int o1, int o2, int nmat, int K, int N,
                        int flags, int o_res, float* sm, int nb) {
    float* As = sm;           // [32][65]
    float* Bs = sm + 2080;    // [32][64]
    int tid = threadIdx.x;
    int tpm = 4 * (N >> 6);
    int total = nmat * tpm;
    for (int tile = blockIdx.x; tile < total; tile += nb) {
        int mat = tile / tpm, ti = tile % tpm;
        int mt = (ti & 3) * 64, nt = (ti >> 2) * 64;
        const float* W = (mat == 0) ? W0 : ((mat == 1) ? W1 : W2);
        int oc = (mat == 0) ? o0 : ((mat == 1) ? o1 : o2);
        const float* A = g_s + o_a;
        float acc[4][4];
#pragma unroll
        for (int i = 0; i < 4; i++)
#pragma unroll
            for (int j = 0; j < 4; j++) acc[i][j] = 0.f;
        int ty = (tid >> 4) << 2, tx = (tid & 15) << 2;
        for (int k0 = 0; k0 < K; k0 += 32) {
            for (int i = tid; i < 512; i += NT) {
                int m = i >> 3, k4 = i & 7;
                float4 v = *(const float4*)&A[(long)(mt + m) * K + k0 + k4 * 4];
                As[(k4 * 4 + 0) * 65 + m] = v.x;
                As[(k4 * 4 + 1) * 65 + m] = v.y;
                As[(k4 * 4 + 2) * 65 + m] = v.z;
                As[(k4 * 4 + 3) * 65 + m] = v.w;
            }
            for (int i = tid; i < 512; i += NT) {
                int kk = i >> 4, n4 = i & 15;
                *(float4*)&Bs[kk * 64 + n4 * 4] =
                    *(const float4*)&W[(long)(k0 + kk) * N + nt + n4 * 4];
            }
            __syncthreads();
#pragma unroll
            for (int kk = 0; kk < 32; kk++) {
                float a0 = As[kk * 65 + ty + 0];
                float a1 = As[kk * 65 + ty + 1];
                float a2 = As[kk * 65 + ty + 2];
                float a3 = As[kk * 65 + ty + 3];
                float4 b = *(float4*)&Bs[kk * 64 + tx];
                acc[0][0] += a0 * b.x; acc[0][1] += a0 * b.y; acc[0][2] += a0 * b.z; acc[0][3] += a0 * b.w;
                acc[1][0] += a1 * b.x; acc[1][1] += a1 * b.y; acc[1][2] += a1 * b.z; acc[1][3] += a1 * b.w;
                acc[2][0] += a2 * b.x; acc[2][1] += a2 * b.y; acc[2][2] += a2 * b.z; acc[2][3] += a2 * b.w;
                acc[3][0] += a3 * b.x; acc[3][1] += a3 * b.y; acc[3][2] += a3 * b.z; acc[3][3] += a3 * b.w;
            }
            __syncthreads();
        }
#pragma unroll
        for (int i = 0; i < 4; i++)
#pragma unroll
            for (int j = 0; j < 4; j++) {
                long idx = (long)(mt + ty + i) * N + nt + tx + j;
                float v = acc[i][j];
                if (flags & 2) v += g_s[o_res + idx];
                if (flags & 1) v = fmaxf(v, 0.f);
                g_s[oc + idx] = v;
            }
    }
}

// ---- encoder attention: 32 units (b,h) ----
__device__ void d_enc_attn(const float* __restrict__ mask, float* sm, int nb) {
    float* Qs = sm; float* Ks = sm + 4096; float* Vs = sm + 8192;
    int tid = threadIdx.x;
    for (int u = blockIdx.x; u < 32; u += nb) {
        int b = u >> 3, h = u & 7;
        for (int i = tid; i < 4096; i += NT) {
            int t = i >> 6, d = i & 63;
            long base = (long)(b * 64 + t) * Dc + h * 64 + d;
            Qs[i] = g_s[O_Q + base];
            Ks[i] = g_s[O_K + base];
            Vs[i] = g_s[O_V + base];
        }
        __syncthreads();
        int q = tid >> 2, j0 = (tid & 3) << 4;
        float sc[16];
#pragma unroll
        for (int i = 0; i < 16; i++) {
            int j = j0 + i;
            float s = 0.f;
#pragma unroll
            for (int d = 0; d < 64; d++) s += Qs[q * 64 + d] * Ks[j * 64 + d];
            sc[i] = s * 0.125f + (1.0f - mask[b * Sc + j]) * NEGB;
        }
        float mx = -3.4e38f;
#pragma unroll
        for (int i = 0; i < 16; i++) mx = fmaxf(mx, sc[i]);
        mx = fmaxf(mx, __shfl_xor_sync(0xffffffffu, mx, 1));
        mx = fmaxf(mx, __shfl_xor_sync(0xffffffffu, mx, 2));
        float sum = 0.f;
#pragma unroll
        for (int i = 0; i < 16; i++) { sc[i] = expf(sc[i] - mx); sum += sc[i]; }
        sum += __shfl_xor_sync(0xffffffffu, sum, 1);
        sum += __shfl_xor_sync(0xffffffffu, sum, 2);
        float inv = 1.0f / sum;
        __syncthreads();
#pragma unroll
        for (int i = 0; i < 16; i++) Qs[q * 64 + j0 + i] = sc[i] * inv;
        __syncthreads();
        int d0 = (tid & 3) << 4;
#pragma unroll
        for (int i = 0; i < 16; i++) {
            int d = d0 + i;
            float o = 0.f;
#pragma unroll
            for (int j = 0; j < 64; j++) o += Qs[q * 64 + j] * Vs[j * 64 + d];
            g_s[O_ATTN + (long)(b * 64 + q) * Dc + h * 64 + d] = o;
        }
        __syncthreads();   // WAR guard before next stride reloads Qs/Ks/Vs
    }
}

// ---- fused rmsnorm + up to 3 GEMVs (M=4, K=512) ----
__device__ void d_gemv_ln3(int o_x, const float* __restrict__ lnw,
                           const float* W0, const float* W1, const float* W2,
                           int o0, int o1, int o2, int os0, int os1, int os2,
                           int N, int nmat, int relu, float* sm, int nb) {
    float* xn = sm;           // 2048
    float* red = sm + 2048;   // 1024
    float* inv = sm + 3072;   // 4
    int tid = threadIdx.x;
    for (int i = tid; i < 2048; i += NT) xn[i] = g_s[o_x + i];
    __syncthreads();
    int wid = tid >> 5, lane = tid & 31;
    if (wid < 4) {
        float ss = 0.f;
#pragma unroll
        for (int i = 0; i < 16; i++) { float v = xn[wid * 512 + lane + 32 * i]; ss += v * v; }
#pragma unroll
        for (int k = 16; k; k >>= 1) ss += __shfl_xor_sync(0xffffffffu, ss, k);
        if (lane == 0) inv[wid] = rsqrtf(ss * (1.0f / 512.0f) + 1e-6f);
    }
    __syncthreads();
    for (int i = tid; i < 2048; i += NT) { int r = i >> 9, c = i & 511; xn[i] *= inv[r] * lnw[c]; }
    __syncthreads();
    int cpm = N >> 6;
    int total = nmat * cpm;
    for (int ch = blockIdx.x; ch < total; ch += nb) {
        int mat = ch / cpm, ci = ch % cpm;
        const float* W = (mat == 0) ? W0 : ((mat == 1) ? W1 : W2);
        int oo = (mat == 0) ? o0 : ((mat == 1) ? o1 : o2);
        int os = (mat == 0) ? os0 : ((mat == 1) ? os1 : os2);
        int col = ci * 64 + (tid & 63);
        int ks = tid >> 6;
        float a0 = 0.f, a1 = 0.f, a2 = 0.f, a3 = 0.f;
        const float* Wp = W + col;
#pragma unroll 8
        for (int k = ks * 128; k < ks * 128 + 128; k++) {
            float w = Wp[(long)k * N];
            a0 += xn[k] * w; a1 += xn[512 + k] * w; a2 += xn[1024 + k] * w; a3 += xn[1536 + k] * w;
        }
        int cl = tid & 63;
        red[ks * 256 + 0 * 64 + cl] = a0;
        red[ks * 256 + 1 * 64 + cl] = a1;
        red[ks * 256 + 2 * 64 + cl] = a2;
        red[ks * 256 + 3 * 64 + cl] = a3;
        __syncthreads();
        if (tid < 64) {
#pragma unroll
            for (int r = 0; r < 4; r++) {
                float s = red[r * 64 + tid] + red[256 + r * 64 + tid]
                        + red[512 + r * 64 + tid] + red[768 + r * 64 + tid];
                if (relu) s = fmaxf(s, 0.f);
                g_s[oo + (long)r * os + ci * 64 + tid] = s;
            }
        }
        __syncthreads();
    }
}

// ---- plain GEMV (M=4, N=512) with += residual; 8 units ----
__device__ void d_gemv_res(int o_x, const float* __restrict__ W, int o_out, int K, float* sm, int nb) {
    float* xs = sm;           // up to 8192
    float* red = sm + 8192;   // 1024
    int tid = threadIdx.x;
    for (int i = tid; i < 4 * K; i += NT) xs[i] = g_s[o_x + i];
    __syncthreads();
    for (int u = blockIdx.x; u < 8; u += nb) {
        int col = u * 64 + (tid & 63);
        int ks = tid >> 6, kc = K >> 2;
        float a0 = 0.f, a1 = 0.f, a2 = 0.f, a3 = 0.f;
        const float* Wp = W + col;
#pragma unroll 8
        for (int k = ks * kc; k < ks * kc + kc; k++) {
            float w = Wp[(long)k * 512];
            a0 += xs[k] * w; a1 += xs[K + k] * w; a2 += xs[2 * K + k] * w; a3 += xs[3 * K + k] * w;
        }
        int cl = tid & 63;
        red[ks * 256 + 0 * 64 + cl] = a0;
        red[ks * 256 + 1 * 64 + cl] = a1;
        red[ks * 256 + 2 * 64 + cl] = a2;
        red[ks * 256 + 3 * 64 + cl] = a3;
        __syncthreads();
        if (tid < 64) {
#pragma unroll
            for (int r = 0; r < 4; r++) {
                float s = red[r * 64 + tid] + red[256 + r * 64 + tid]
                        + red[512 + r * 64 + tid] + red[768 + r * 64 + tid];
                g_s[o_out + r * 512 + u * 64 + tid] += s;
            }
        }
        __syncthreads();   // WAR guard for red reuse
    }
}

// ---- single-token attention; 32 units ----
__device__ void d_attn_step(int o_q, int o_kc, int o_vc, int bstride, int count,
                            const float* mask, int o_out, float* sm, int nb) {
    float* p = sm;
    for (int u = blockIdx.x; u < 32; u += nb) {
        int b = u >> 3, h = u & 7;
        int j = threadIdx.x;
        const float* Kp = g_s + o_kc + (long)b * bstride;
        const float* Vp = g_s + o_vc + (long)b * bstride;
        const float* q = g_s + o_q + b * 512 + h * 64;
        if (j < count) {
            float s = 0.f;
#pragma unroll 8
            for (int d = 0; d < 64; d++) s += q[d] * Kp[(long)j * 512 + h * 64 + d];
            s *= 0.125f;
            if (mask) s += (1.0f - mask[b * Sc + j]) * NEGB;
            p[j] = s;
        }
        __syncthreads();
        float mx = -3.4e38f;
        for (int jj = 0; jj < count; jj++) mx = fmaxf(mx, p[jj]);
        float sum = 0.f;
        for (int jj = 0; jj < count; jj++) sum += expf(p[jj] - mx);
        __syncthreads();
        if (j < count) p[j] = expf(p[j] - mx) / sum;
        __syncthreads();
        if (j < 64) {
            float o = 0.f;
            for (int jj = 0; jj < count; jj++) o += p[jj] * Vp[(long)jj * 512 + h * 64 + j];
            g_s[o_out + b * 512 + h * 64 + j] = o;
        }
        __syncthreads();   // WAR guard for p reuse
    }
}

// ---- softmax over V: 128 units = 4 rows x 32 slices ----
__device__ void d_softmax1(float* sm, int nb) {
    int tid = threadIdx.x;
    for (int u = blockIdx.x; u < 128; u += nb) {
        int r = u >> 5, s = u & 31;
        const float* lg = g_s + O_LOGITS + (long)r * Vc + s * 1004;
        float mx = -3.4e38f; int arg = 0;
        for (int v = tid; v < 1004; v += NT) {
            float x = lg[v];
            if (x > mx) { mx = x; arg = v; }
        }
        sm[tid] = mx; ((int*)sm)[256 + tid] = arg;
        __syncthreads();
        for (int st = 128; st; st >>= 1) {
            if (tid < st) {
                float o = sm[tid + st]; int oa = ((int*)sm)[256 + tid + st];
                if (o > sm[tid] || (o == sm[tid] && oa < ((int*)sm)[256 + tid])) {
                    sm[tid] = o; ((int*)sm)[256 + tid] = oa;
                }
            }
            __syncthreads();
        }
        if (tid == 0) {
            g_s[O_SMAX + r * 32 + s] = sm[0];
            ((int*)g_s)[O_SARG + r * 32 + s] = ((int*)sm)[256] + s * 1004;
        }
        __syncthreads();
    }
}

__device__ void d_softmax2(float* sm, int nb) {
    int tid = threadIdx.x;
    for (int u = blockIdx.x; u < 128; u += nb) {
        int r = u >> 5, s = u & 31;
        float gmax = -3.4e38f;
#pragma unroll
        for (int i = 0; i < 32; i++) gmax = fmaxf(gmax, g_s[O_SMAX + r * 32 + i]);
        const float* lg = g_s + O_LOGITS + (long)r * Vc + s * 1004;
        float sum = 0.f;
        for (int v = tid; v < 1004; v += NT) sum += expf(lg[v] - gmax);
        sm[tid] = sum;
        __syncthreads();
        for (int st = 128; st; st >>= 1) {
            if (tid < st) sm[tid] += sm[tid + st];
            __syncthreads();
        }
        if (tid == 0) g_s[O_SSUM + r * 32 + s] = sm[0];
        __syncthreads();
    }
}

__device__ void d_softmax3(float* out, int iter, int nb) {
    for (int u = blockIdx.x; u < 128; u += nb) {
        int r = u >> 5, s = u & 31;
        float gmax = -3.4e38f;
#pragma unroll
        for (int i = 0; i < 32; i++) gmax = fmaxf(gmax, g_s[O_SMAX + r * 32 + i]);
        float tot = 0.f;
#pragma unroll
        for (int i = 0; i < 32; i++) tot += g_s[O_SSUM + r * 32 + i];
        float inv = 1.0f / tot;
        const float* lg = g_s + O_LOGITS + (long)r * Vc + s * 1004;
        float* po = out + ((long)r * Tc + iter) * Vc + s * 1004;
        for (int v = threadIdx.x; v < 1004; v += NT) po[v] = expf(lg[v] - gmax) * inv;
        if (s == 0 && threadIdx.x == 0) {
            float bm = -3.4e38f; int ba = 0;
            for (int i = 0; i < 32; i++) {
                float m = g_s[O_SMAX + r * 32 + i];
                int a = ((int*)g_s)[O_SARG + r * 32 + i];
                if (m > bm || (m == bm && a < ba)) { bm = m; ba = a; }
            }
            out[(long)Bc * Tc * Vc + r * Tc + iter] = (ba == 0) ? 1.0f : 0.0f;
        }
    }
}

// ---- probs @ emb -> DX; 64 units x 8 cols ----
__device__ void d_pemb(const float* out, const float* __restrict__ emb, int iter, float* sm, int nb) {
    int tid = threadIdx.x;
    for (int u = blockIdx.x; u < 64; u += nb) {
        int c0 = u * 8;
        int cl = tid & 7, ksl = tid >> 3;
        int col = c0 + cl;
        const float* p0 = out + ((long)0 * Tc + iter) * Vc;
        const float* p1 = out + ((long)1 * Tc + iter) * Vc;
        const float* p2 = out + ((long)2 * Tc + iter) * Vc;
        const float* p3 = out + ((long)3 * Tc + iter) * Vc;
        float a0 = 0.f, a1 = 0.f, a2 = 0.f, a3 = 0.f;
        int v0 = ksl * 1004;
#pragma unroll 4
        for (int v = v0; v < v0 + 1004; v++) {
            float e = emb[(long)v * 512 + col];
            a0 += p0[v] * e; a1 += p1[v] * e; a2 += p2[v] * e; a3 += p3[v] * e;
        }
        sm[(0 * 32 + ksl) * 8 + cl] = a0;
        sm[(1 * 32 + ksl) * 8 + cl] = a1;
        sm[(2 * 32 + ksl) * 8 + cl] = a2;
        sm[(3 * 32 + ksl) * 8 + cl] = a3;
        __syncthreads();
        if (tid < 32) {
            int r = tid >> 3, c = tid & 7;
            float ssum = 0.f;
            for (int k = 0; k < 32; k++) ssum += sm[(r * 32 + k) * 8 + c];
            g_s[O_DX + r * 512 + c0 + c] = ssum;
        }
        __syncthreads();
    }
}

// ---- the megakernel ----
__global__ void __launch_bounds__(NT) k_mega(P p, int nb) {
    __shared__ float sm[12288];   // 48 KB
    int tid = threadIdx.x, bid = blockIdx.x;

    for (int i = bid * NT + tid; i < 256 * Dc; i += nb * NT) {
        int r = i >> 9;
        g_s[O_X + i] = p.emb[(long)p.ids[r] * Dc + (i & 511)];
    }
    gsync(nb);

    // ===== encoder =====
    for (int l = 0; l < Lc; l++) {
        d_rmsnorm(O_X, p.eln1 + l * Dc, O_H, nb); gsync(nb);
        d_gemm3(O_H, p.ewq + l * DD, p.ewk + l * DD, p.ewv + l * DD,
                O_Q, O_K, O_V, 3, 512, 512, 0, 0, sm, nb); gsync(nb);
        d_enc_attn(p.mask, sm, nb); gsync(nb);
        d_gemm3(O_ATTN, p.ewo + l * DD, 0, 0, O_X, 0, 0, 1, 512, 512, 2, O_X, sm, nb); gsync(nb);
        d_rmsnorm(O_X, p.eln2 + l * Dc, O_H, nb); gsync(nb);
        d_gemm3(O_H, p.ew1 + l * DF, 0, 0, O_FF, 0, 0, 1, 512, 2048, 1, 0, sm, nb); gsync(nb);
        d_gemm3(O_FF, p.ew2 + l * DF, 0, 0, O_X, 0, 0, 1, 2048, 512, 2, O_X, sm, nb); gsync(nb);
    }
    d_rmsnorm(O_X, p.elnf, O_HS, nb); gsync(nb);
    for (int l = 0; l < Lc; l++) {
        d_gemm3(O_HS, p.dck + l * DD, p.dcv + l * DD, 0,
                O_ENCK + l * 131072, O_ENCV + l * 131072, 0, 2, 512, 512, 0, 0, sm, nb); gsync(nb);
    }

    for (int i = bid * NT + tid; i < 2048; i += nb * NT) g_s[O_DX + i] = p.emb[i & 511];
    gsync(nb);

    // ===== decode loop (KV-cached) =====
    for (int t = 0; t < Tc; t++) {
        for (int l = 0; l < Lc; l++) {
            d_gemv_ln3(O_DX, p.dln1 + l * Dc, p.dsq + l * DD, p.dsk + l * DD, p.dsv + l * DD,
                       O_DQ, O_SK + l * 32768 + t * 512, O_SV + l * 32768 + t * 512,
                       512, 8192, 8192, 512, 3, 0, sm, nb); gsync(nb);
            d_attn_step(O_DQ, O_SK + l * 32768, O_SV + l * 32768, 8192, t + 1, 0, O_DATTN, sm, nb); gsync(nb);
            d_gemv_res(O_DATTN, p.dso + l * DD, O_DX, 512, sm, nb); gsync(nb);
            d_gemv_ln3(O_DX, p.dln2 + l * Dc, p.dcq + l * DD, 0, 0,
                       O_DQ, 0, 0, 512, 0, 0, 512, 1, 0, sm, nb); gsync(nb);
            d_attn_step(O_DQ, O_ENCK + l * 131072, O_ENCV + l * 131072, 32768, 64, p.mask, O_DATTN, sm, nb); gsync(nb);
            d_gemv_res(O_DATTN, p.dco + l * DD, O_DX, 512, sm, nb); gsync(nb);
            d_gemv_ln3(O_DX, p.dln3 + l * Dc, p.dw1 + l * DF, 0, 0,
                       O_DFF, 0, 0, 2048, 0, 0, 2048, 1, 1, sm, nb); gsync(nb);
            d_gemv_res(O_DFF, p.dw2 + l * DF, O_DX, 2048, sm, nb); gsync(nb);
        }
        d_gemv_ln3(O_DX, p.dlnf, p.lm, 0, 0, O_LOGITS, 0, 0, Vc, 0, 0, Vc, 1, 0, sm, nb); gsync(nb);
        d_softmax1(sm, nb); gsync(nb);
        d_softmax2(sm, nb); gsync(nb);
        d_softmax3(p.out, t, nb); gsync(nb);
        d_pemb(p.out, p.emb, t, sm, nb); gsync(nb);
    }
}

// ---- host ----
extern "C" void kernel_launch(void* const* d_in, const int* in_sizes, int n_in,
                              void* d_out, int out_size) {
    (void)in_sizes; (void)n_in; (void)out_size;
    P p;
    p.ids  = (const int*)d_in[0];
    p.mask = (const float*)d_in[1];
    p.emb  = (const float*)d_in[2];
    p.ewq  = (const float*)d_in[3];
    p.ewk  = (const float*)d_in[4];
    p.ewv  = (const float*)d_in[5];
    p.ewo  = (const float*)d_in[6];
    p.eln1 = (const float*)d_in[7];
    p.ew1  = (const float*)d_in[8];
    p.ew2  = (const float*)d_in[9];
    p.eln2 = (const float*)d_in[10];
    p.elnf = (const float*)d_in[11];
    p.dsq  = (const float*)d_in[12];
    p.dsk  = (const float*)d_in[13];
    p.dsv  = (const float*)d_in[14];
    p.dso  = (const float*)d_in[15];
    p.dln1 = (const float*)d_in[16];
    p.dcq  = (const float*)d_in[17];
    p.dck  = (const float*)d_in[18];
    p.dcv  = (const float*)d_in[19];
    p.dco  = (const float*)d_in[20];
    p.dln2 = (const float*)d_in[21];
    p.dw1  = (const float*)d_in[22];
    p.dw2  = (const float*)d_in[23];
    p.dln3 = (const float*)d_in[24];
    p.dlnf = (const float*)d_in[25];
    p.lm   = (const float*)d_in[26];
    p.out  = (float*)d_out;

    // size the persistent grid from the ACTUAL device (single-wave residency guaranteed)
    int dev = 0;
    cudaGetDevice(&dev);
    int sms = 0;
    cudaDeviceGetAttribute(&sms, cudaDevAttrMultiProcessorCount, dev);
    int bpm = 0;
    cudaOccupancyMaxActiveBlocksPerMultiprocessor(&bpm, k_mega, NT, 0);
    int nb = sms * bpm;
    if (nb > NBMAX) nb = NBMAX;
    if (nb < 1) nb = 1;
    k_mega<<<nb, NT>>>(p, nb);
}

// round 12
// speedup vs baseline: 2.3979x; 2.0263x over previous
#include <cuda_runtime.h>
#include <math.h>

#define NBMAX 128
#define NT 256
#define Dc 512
#define Hc 8
#define DFFc 2048
#define Lc 2
#define Vc 32128
#define Tc 16
#define Bc 4
#define Sc 64
#define NEGB (-1e9f)

#define DD (512*512)
#define DF (512*2048)

// ---- scratch layout (floats) ----
#define O_X      0
#define O_H      131072
#define O_Q      262144
#define O_K      393216
#define O_V      524288
#define O_ATTN   655360
#define O_HS     786432
#define O_FF     917504
#define O_ENCK   1441792
#define O_ENCV   1703936
#define O_DX     1966080
#define O_DQ     1968128
#define O_DATTN  1970176
#define O_DFF    1972224
#define O_SK     1980416
#define O_SV     2045952
#define O_LOGITS 2111488
#define O_SMAX   2240000
#define O_SARG   2240128
#define O_SSUM   2240256
#define O_PP     2240512    // 32 * 2048 split-K partials
#define SCRATCH  2306048

__device__ float g_s[SCRATCH];
__device__ volatile unsigned g_flag[NBMAX];
__device__ volatile unsigned g_gen;

// ---- flag-tree grid barrier: plain stores + parallel poll (no contended atomics) ----
__device__ __forceinline__ void gsync(int nb, unsigned* s_gen) {
    __syncthreads();
    unsigned target = *s_gen + 1u;
    if (threadIdx.x == 0) {
        __threadfence();
        g_flag[blockIdx.x] = target;          // arrive (distinct address per block)
    }
    if (blockIdx.x == 0) {
        for (int j = threadIdx.x; j < nb; j += NT)
            while ((int)(g_flag[j] - target) < 0) __nanosleep(32);
        __syncthreads();
        if (threadIdx.x == 0) {
            __threadfence();
            g_gen = target;                   // release
            *s_gen = target;
        }
        __syncthreads();
    } else {
        if (threadIdx.x == 0) {
            while ((int)(g_gen - target) < 0) __nanosleep(64);
            __threadfence();
            *s_gen = target;
        }
        __syncthreads();
    }
}

struct P {
    const int* ids; const float* mask; const float* emb;
    const float *ewq, *ewk, *ewv, *ewo, *eln1, *ew1, *ew2, *eln2, *elnf;
    const float *dsq, *dsk, *dsv, *dso, *dln1;
    const float *dcq, *dck, *dcv, *dco, *dln2;
    const float *dw1, *dw2, *dln3, *dlnf, *lm;
    float* out;
};

// ---- rmsnorm over 256 rows ----
__device__ void d_rmsnorm(int o_in, const float* __restrict__ w, int o_out, int nb) {
    int wid = threadIdx.x >> 5, lane = threadIdx.x & 31;
    for (int u = blockIdx.x; u < 32; u += nb) {
        int row = u * 8 + wid;
        const float* x = g_s + o_in + row * Dc;
        float ss = 0.f;
#pragma unroll
        for (int i = 0; i < 16; i++) { float v = x[lane + 32 * i]; ss += v * v; }
#pragma unroll
        for (int k = 16; k; k >>= 1) ss += __shfl_xor_sync(0xffffffffu, ss, k);
        float inv = rsqrtf(ss * (1.0f / Dc) + 1e-6f);
        float* o = g_s + o_out + row * Dc;
#pragma unroll
        for (int i = 0; i < 16; i++) { int c = lane + 32 * i; o[c] = x[c] * inv * w[c]; }
    }
}

// ---- encoder GEMM: up to 3 matrices, M=256, tile 64x64, k-chunk 32 ----
__device__ void d_gemm3(int o_a, const float* W0, const float* W1, const float* W2,
                        int o0, int o1, int o2, int nmat, int K, int N,
                        int flags, int o_res, float* sm, int nb) {
    float* As = sm;           // [32][65]
    float* Bs = sm + 2080;    // [32][64]
    int tid = threadIdx.x;
    int tpm = 4 * (N >> 6);
    int total = nmat * tpm;
    for (int tile = blockIdx.x; tile < total; tile += nb) {
        int mat = tile / tpm, ti = tile % tpm;
        int mt = (ti & 3) * 64, nt = (ti >> 2) * 64;
        const float* W = (mat == 0) ? W0 : ((mat == 1) ? W1 : W2);
        int oc = (mat == 0) ? o0 : ((mat == 1) ? o1 : o2);
        const float* A = g_s + o_a;
        float acc[4][4];
#pragma unroll
        for (int i = 0; i < 4; i++)
#pragma unroll
            for (int j = 0; j < 4; j++) acc[i][j] = 0.f;
        int ty = (tid >> 4) << 2, tx = (tid & 15) << 2;
        for (int k0 = 0; k0 < K; k0 += 32) {
            for (int i = tid; i < 512; i += NT) {
                int m = i >> 3, k4 = i & 7;
                float4 v = *(const float4*)&A[(long)(mt + m) * K + k0 + k4 * 4];
                As[(k4 * 4 + 0) * 65 + m] = v.x;
                As[(k4 * 4 + 1) * 65 + m] = v.y;
                As[(k4 * 4 + 2) * 65 + m] = v.z;
                As[(k4 * 4 + 3) * 65 + m] = v.w;
            }
            for (int i = tid; i < 512; i += NT) {
                int kk = i >> 4, n4 = i & 15;
                *(float4*)&Bs[kk * 64 + n4 * 4] =
                    *(const float4*)&W[(long)(k0 + kk) * N + nt + n4 * 4];
            }
            __syncthreads();
#pragma unroll
            for (int kk = 0; kk < 32; kk++) {
                float a0 = As[kk * 65 + ty + 0];
                float a1 = As[kk * 65 + ty + 1];
                float a2 = As[kk * 65 + ty + 2];
                float a3 = As[kk * 65 + ty + 3];
                float4 b = *(float4*)&Bs[kk * 64 + tx];
                acc[0][0] += a0 * b.x; acc[0][1] += a0 * b.y; acc[0][2] += a0 * b.z; acc[0][3] += a0 * b.w;
                acc[1][0] += a1 * b.x; acc[1][1] += a1 * b.y; acc[1][2] += a1 * b.z; acc[1][3] += a1 * b.w;
                acc[2][0] += a2 * b.x; acc[2][1] += a2 * b.y; acc[2][2] += a2 * b.z; acc[2][3] += a2 * b.w;
                acc[3][0] += a3 * b.x; acc[3][1] += a3 * b.y; acc[3][2] += a3 * b.z; acc[3][3] += a3 * b.w;
            }
            __syncthreads();
        }
#pragma unroll
        for (int i = 0; i < 4; i++)
#pragma unroll
            for (int j = 0; j < 4; j++) {
                long idx = (long)(mt + ty + i) * N + nt + tx + j;
                float v = acc[i][j];
                if (flags & 2) v += g_s[o_res + idx];
                if (flags & 1) v = fmaxf(v, 0.f);
                g_s[oc + idx] = v;
            }
    }
}

// ---- encoder attention: 32 units (b,h) ----
__device__ void d_enc_attn(const float* __restrict__ mask, float* sm, int nb) {
    float* Qs = sm; float* Ks = sm + 4096; float* Vs = sm + 8192;
    int tid = threadIdx.x;
    for (int u = blockIdx.x; u < 32; u += nb) {
        int b = u >> 3, h = u & 7;
        for (int i = tid; i < 4096; i += NT) {
            int t = i >> 6, d = i & 63;
            long base = (long)(b * 64 + t) * Dc + h * 64 + d;
            Qs[i] = g_s[O_Q + base];
            Ks[i] = g_s[O_K + base];
            Vs[i] = g_s[O_V + base];
        }
        __syncthreads();
        int q = tid >> 2, j0 = (tid & 3) << 4;
        float sc[16];
#pragma unroll
        for (int i = 0; i < 16; i++) {
            int j = j0 + i;
            float s = 0.f;
#pragma unroll
            for (int d = 0; d < 64; d++) s += Qs[q * 64 + d] * Ks[j * 64 + d];
            sc[i] = s * 0.125f + (1.0f - mask[b * Sc + j]) * NEGB;
        }
        float mx = -3.4e38f;
#pragma unroll
        for (int i = 0; i < 16; i++) mx = fmaxf(mx, sc[i]);
        mx = fmaxf(mx, __shfl_xor_sync(0xffffffffu, mx, 1));
        mx = fmaxf(mx, __shfl_xor_sync(0xffffffffu, mx, 2));
        float sum = 0.f;
#pragma unroll
        for (int i = 0; i < 16; i++) { sc[i] = expf(sc[i] - mx); sum += sc[i]; }
        sum += __shfl_xor_sync(0xffffffffu, sum, 1);
        sum += __shfl_xor_sync(0xffffffffu, sum, 2);
        float inv = 1.0f / sum;
        __syncthreads();
#pragma unroll
        for (int i = 0; i < 16; i++) Qs[q * 64 + j0 + i] = sc[i] * inv;
        __syncthreads();
        int d0 = (tid & 3) << 4;
#pragma unroll
        for (int i = 0; i < 16; i++) {
            int d = d0 + i;
            float o = 0.f;
#pragma unroll
            for (int j = 0; j < 64; j++) o += Qs[q * 64 + j] * Vs[j * 64 + d];
            g_s[O_ATTN + (long)(b * 64 + q) * Dc + h * 64 + d] = o;
        }
        __syncthreads();
    }
}

// ---- fused rmsnorm + up to 3 GEMVs, M=4, K=512; 128-col strips, 8-warp k-split, float4 ----
__device__ void d_gemv_ln3(int o_x, const float* __restrict__ lnw,
                           const float* W0, const float* W1, const float* W2,
                           int o0, int o1, int o2, int os0, int os1, int os2,
                           int N, int nmat, int relu, float* sm, int nb) {
    float* xn = sm;           // 2048
    float* red = sm + 2048;   // 4096
    float* inv = sm + 6144;   // 4
    int tid = threadIdx.x, wid = tid >> 5, lane = tid & 31;
    for (int i = tid; i < 2048; i += NT) xn[i] = g_s[o_x + i];
    __syncthreads();
    if (wid < 4) {
        float ss = 0.f;
#pragma unroll
        for (int i = 0; i < 16; i++) { float v = xn[wid * 512 + lane + 32 * i]; ss += v * v; }
#pragma unroll
        for (int k = 16; k; k >>= 1) ss += __shfl_xor_sync(0xffffffffu, ss, k);
        if (lane == 0) inv[wid] = rsqrtf(ss * (1.0f / 512.0f) + 1e-6f);
    }
    __syncthreads();
    for (int i = tid; i < 2048; i += NT) xn[i] *= inv[i >> 9] * lnw[i & 511];
    __syncthreads();
    int spm = N >> 7;
    int total = nmat * spm;
    for (int st = blockIdx.x; st < total; st += nb) {
        int mat = st / spm, si = st - mat * spm;
        const float* W = (mat == 0) ? W0 : ((mat == 1) ? W1 : W2);
        int oo = (mat == 0) ? o0 : ((mat == 1) ? o1 : o2);
        int os = (mat == 0) ? os0 : ((mat == 1) ? os1 : os2);
        long cb = (long)(si << 7) + (lane << 2);
        float4 a0 = make_float4(0, 0, 0, 0), a1 = a0, a2 = a0, a3 = a0;
        int k0 = wid << 6;
#pragma unroll 8
        for (int k = k0; k < k0 + 64; k++) {
            float4 w = *(const float4*)(W + (long)k * N + cb);
            float x0 = xn[k], x1 = xn[512 + k], x2 = xn[1024 + k], x3 = xn[1536 + k];
            a0.x += x0 * w.x; a0.y += x0 * w.y; a0.z += x0 * w.z; a0.w += x0 * w.w;
            a1.x += x1 * w.x; a1.y += x1 * w.y; a1.z += x1 * w.z; a1.w += x1 * w.w;
            a2.x += x2 * w.x; a2.y += x2 * w.y; a2.z += x2 * w.z; a2.w += x2 * w.w;
            a3.x += x3 * w.x; a3.y += x3 * w.y; a3.z += x3 * w.z; a3.w += x3 * w.w;
        }
        *(float4*)&red[wid * 512 + 0   + (lane << 2)] = a0;
        *(float4*)&red[wid * 512 + 128 + (lane << 2)] = a1;
        *(float4*)&red[wid * 512 + 256 + (lane << 2)] = a2;
        *(float4*)&red[wid * 512 + 384 + (lane << 2)] = a3;
        __syncthreads();
        for (int o = tid; o < 512; o += NT) {
            int r = o >> 7, c = o & 127;
            float s = 0.f;
#pragma unroll
            for (int w8 = 0; w8 < 8; w8++) s += red[w8 * 512 + r * 128 + c];
            if (relu) s = fmaxf(s, 0.f);
            g_s[oo + (long)r * os + (si << 7) + c] = s;
        }
        __syncthreads();
    }
}

// ---- GEMV (M=4, N=512), 128-col strips, optional cross-block k-split ----
__device__ void d_gemv_res(int o_x, const float* __restrict__ W, int o_out, int K, int nkc,
                           float* sm, int nb) {
    float* xs = sm;           // 4*K (<= 8192)
    float* red = sm + 8192;   // 4096
    int tid = threadIdx.x, wid = tid >> 5, lane = tid & 31;
    for (int i = tid; i < 4 * K; i += NT) xs[i] = g_s[o_x + i];
    __syncthreads();
    int tasks = 4 * nkc;
    int kpb = K / nkc, kpw = kpb >> 3;
    for (int st = blockIdx.x; st < tasks; st += nb) {
        int si = st & 3, kc = st >> 2;
        long cb = (long)(si << 7) + (lane << 2);
        float4 a0 = make_float4(0, 0, 0, 0), a1 = a0, a2 = a0, a3 = a0;
        int k0 = kc * kpb + wid * kpw;
#pragma unroll 8
        for (int k = k0; k < k0 + kpw; k++) {
            float4 w = *(const float4*)(W + (long)k * 512 + cb);
            float x0 = xs[k], x1 = xs[K + k], x2 = xs[2 * K + k], x3 = xs[3 * K + k];
            a0.x += x0 * w.x; a0.y += x0 * w.y; a0.z += x0 * w.z; a0.w += x0 * w.w;
            a1.x += x1 * w.x; a1.y += x1 * w.y; a1.z += x1 * w.z; a1.w += x1 * w.w;
            a2.x += x2 * w.x; a2.y += x2 * w.y; a2.z += x2 * w.z; a2.w += x2 * w.w;
            a3.x += x3 * w.x; a3.y += x3 * w.y; a3.z += x3 * w.z; a3.w += x3 * w.w;
        }
        *(float4*)&red[wid * 512 + 0   + (lane << 2)] = a0;
        *(float4*)&red[wid * 512 + 128 + (lane << 2)] = a1;
        *(float4*)&red[wid * 512 + 256 + (lane << 2)] = a2;
        *(float4*)&red[wid * 512 + 384 + (lane << 2)] = a3;
        __syncthreads();
        for (int o = tid; o < 512; o += NT) {
            int r = o >> 7, c = o & 127;
            float s = 0.f;
#pragma unroll
            for (int w8 = 0; w8 < 8; w8++) s += red[w8 * 512 + r * 128 + c];
            if (nkc == 1) g_s[o_out + r * 512 + (si << 7) + c] += s;
            else g_s[O_PP + kc * 2048 + r * 512 + (si << 7) + c] = s;
        }
        __syncthreads();
    }
}

// ---- reduce split-K partials (mode 1: += into o_out, mode 0: overwrite) ----
__device__ void d_ppred(int nkc, int o_out, int add, int nb) {
    for (int idx = blockIdx.x * NT + threadIdx.x; idx < 2048; idx += nb * NT) {
        float s = 0.f;
        for (int kc = 0; kc < nkc; kc++) s += g_s[O_PP + kc * 2048 + idx];
        if (add) g_s[o_out + idx] += s;
        else g_s[o_out + idx] = s;
    }
}

// ---- single-token attention; 32 units ----
__device__ void d_attn_step(int o_q, int o_kc, int o_vc, int bstride, int count,
                            const float* mask, int o_out, float* sm, int nb) {
    float* p = sm;
    for (int u = blockIdx.x; u < 32; u += nb) {
        int b = u >> 3, h = u & 7;
        int j = threadIdx.x;
        const float* Kp = g_s + o_kc + (long)b * bstride;
        const float* Vp = g_s + o_vc + (long)b * bstride;
        const float* q = g_s + o_q + b * 512 + h * 64;
        if (j < count) {
            const float4* K4 = (const float4*)(Kp + (long)j * 512 + h * 64);
            const float4* q4 = (const float4*)q;
            float s = 0.f;
#pragma unroll
            for (int d = 0; d < 16; d++) {
                float4 kv = K4[d], qv = q4[d];
                s += qv.x * kv.x + qv.y * kv.y + qv.z * kv.z + qv.w * kv.w;
            }
            s *= 0.125f;
            if (mask) s += (1.0f - mask[b * Sc + j]) * NEGB;
            p[j] = s;
        }
        __syncthreads();
        float mx = -3.4e38f;
        for (int jj = 0; jj < count; jj++) mx = fmaxf(mx, p[jj]);
        float sum = 0.f;
        for (int jj = 0; jj < count; jj++) sum += expf(p[jj] - mx);
        __syncthreads();
        if (j < count) p[j] = expf(p[j] - mx) / sum;
        __syncthreads();
        if (j < 64) {
            float o = 0.f;
            for (int jj = 0; jj < count; jj++) o += p[jj] * Vp[(long)jj * 512 + h * 64 + j];
            g_s[o_out + b * 512 + h * 64 + j] = o;
        }
        __syncthreads();
    }
}

// ---- softmax over V: 128 units = 4 rows x 32 slices ----
__device__ void d_softmax1(float* sm, int nb) {
    int tid = threadIdx.x;
    for (int u = blockIdx.x; u < 128; u += nb) {
        int r = u >> 5, s = u & 31;
        const float* lg = g_s + O_LOGITS + (long)r * Vc + s * 1004;
        float mx = -3.4e38f; int arg = 0;
        for (int v = tid; v < 1004; v += NT) {
            float x = lg[v];
            if (x > mx) { mx = x; arg = v; }
        }
        sm[tid] = mx; ((int*)sm)[256 + tid] = arg;
        __syncthreads();
        for (int st = 128; st; st >>= 1) {
            if (tid < st) {
                float o = sm[tid + st]; int oa = ((int*)sm)[256 + tid + st];
                if (o > sm[tid] || (o == sm[tid] && oa < ((int*)sm)[256 + tid])) {
                    sm[tid] = o; ((int*)sm)[256 + tid] = oa;
                }
            }
            __syncthreads();
        }
        if (tid == 0) {
            g_s[O_SMAX + r * 32 + s] = sm[0];
            ((int*)g_s)[O_SARG + r * 32 + s] = ((int*)sm)[256] + s * 1004;
        }
        __syncthreads();
    }
}

__device__ void d_softmax2(float* sm, int nb) {
    int tid = threadIdx.x;
    for (int u = blockIdx.x; u < 128; u += nb) {
        int r = u >> 5, s = u & 31;
        float gmax = -3.4e38f;
#pragma unroll
        for (int i = 0; i < 32; i++) gmax = fmaxf(gmax, g_s[O_SMAX + r * 32 + i]);
        const float* lg = g_s + O_LOGITS + (long)r * Vc + s * 1004;
        float sum = 0.f;
        for (int v = tid; v < 1004; v += NT) sum += expf(lg[v] - gmax);
        sm[tid] = sum;
        __syncthreads();
        for (int st = 128; st; st >>= 1) {
            if (tid < st) sm[tid] += sm[tid + st];
            __syncthreads();
        }
        if (tid == 0) g_s[O_SSUM + r * 32 + s] = sm[0];
        __syncthreads();
    }
}

__device__ void d_softmax3(float* out, int iter, int nb) {
    for (int u = blockIdx.x; u < 128; u += nb) {
        int r = u >> 5, s = u & 31;
        float gmax = -3.4e38f;
#pragma unroll
        for (int i = 0; i < 32; i++) gmax = fmaxf(gmax, g_s[O_SMAX + r * 32 + i]);
        float tot = 0.f;
#pragma unroll
        for (int i = 0; i < 32; i++) tot += g_s[O_SSUM + r * 32 + i];
        float inv = 1.0f / tot;
        const float* lg = g_s + O_LOGITS + (long)r * Vc + s * 1004;
        float* po = out + ((long)r * Tc + iter) * Vc + s * 1004;
        for (int v = threadIdx.x; v < 1004; v += NT) po[v] = expf(lg[v] - gmax) * inv;
        if (s == 0 && threadIdx.x == 0) {
            float bm = -3.4e38f; int ba = 0;
            for (int i = 0; i < 32; i++) {
                float m = g_s[O_SMAX + r * 32 + i];
                int a = ((int*)g_s)[O_SARG + r * 32 + i];
                if (m > bm || (m == bm && a < ba)) { bm = m; ba = a; }
            }
            out[(long)Bc * Tc * Vc + r * Tc + iter] = (ba == 0) ? 1.0f : 0.0f;
        }
    }
}

// ---- probs @ emb -> O_PP partials; 128 tasks = 4 strips x 32 k-chunks ----
__device__ void d_pemb(const float* out, const float* __restrict__ emb, int iter, float* sm, int nb) {
    float* red = sm;   // 4096
    int tid = threadIdx.x, wid = tid >> 5, lane = tid & 31;
    for (int task = blockIdx.x; task < 128; task += nb) {
        int si = task & 3, kc = task >> 2;
        int c0 = si << 7;
        int v0 = kc * 1004;
        const float* p0 = out + ((long)0 * Tc + iter) * Vc;
        const float* p1 = out + ((long)1 * Tc + iter) * Vc;
        const float* p2 = out + ((long)2 * Tc + iter) * Vc;
        const float* p3 = out + ((long)3 * Tc + iter) * Vc;
        float4 a0 = make_float4(0, 0, 0, 0), a1 = a0, a2 = a0, a3 = a0;
#pragma unroll 4
        for (int v = v0 + wid; v < v0 + 1004; v += 8) {
            float4 e = *(const float4*)(emb + (long)v * 512 + c0 + (lane << 2));
            float q0 = p0[v], q1 = p1[v], q2 = p2[v], q3 = p3[v];
            a0.x += q0 * e.x; a0.y += q0 * e.y; a0.z += q0 * e.z; a0.w += q0 * e.w;
            a1.x += q1 * e.x; a1.y += q1 * e.y; a1.z += q1 * e.z; a1.w += q1 * e.w;
            a2.x += q2 * e.x; a2.y += q2 * e.y; a2.z += q2 * e.z; a2.w += q2 * e.w;
            a3.x += q3 * e.x; a3.y += q3 * e.y; a3.z += q3 * e.z; a3.w += q3 * e.w;
        }
        *(float4*)&red[wid * 512 + 0   + (lane << 2)] = a0;
        *(float4*)&red[wid * 512 + 128 + (lane << 2)] = a1;
        *(float4*)&red[wid * 512 + 256 + (lane << 2)] = a2;
        *(float4*)&red[wid * 512 + 384 + (lane << 2)] = a3;
        __syncthreads();
        for (int o = tid; o < 512; o += NT) {
            int r = o >> 7, c = o & 127;
            float s = 0.f;
#pragma unroll
            for (int w8 = 0; w8 < 8; w8++) s += red[w8 * 512 + r * 128 + c];
            g_s[O_PP + kc * 2048 + r * 512 + c0 + c] = s;
        }
        __syncthreads();
    }
}

// ---- the megakernel ----
__global__ void __launch_bounds__(NT) k_mega(P p, int nb) {
    __shared__ float sm[12288];
    __shared__ unsigned s_gen;
    int tid = threadIdx.x, bid = blockIdx.x;
    if (tid == 0) s_gen = g_gen;
    __syncthreads();

    for (int i = bid * NT + tid; i < 256 * Dc; i += nb * NT) {
        int r = i >> 9;
        g_s[O_X + i] = p.emb[(long)p.ids[r] * Dc + (i & 511)];
    }
    gsync(nb, &s_gen);

    // ===== encoder =====
    for (int l = 0; l < Lc; l++) {
        d_rmsnorm(O_X, p.eln1 + l * Dc, O_H, nb); gsync(nb, &s_gen);
        d_gemm3(O_H, p.ewq + l * DD, p.ewk + l * DD, p.ewv + l * DD,
                O_Q, O_K, O_V, 3, 512, 512, 0, 0, sm, nb); gsync(nb, &s_gen);
        d_enc_attn(p.mask, sm, nb); gsync(nb, &s_gen);
        d_gemm3(O_ATTN, p.ewo + l * DD, 0, 0, O_X, 0, 0, 1, 512, 512, 2, O_X, sm, nb); gsync(nb, &s_gen);
        d_rmsnorm(O_X, p.eln2 + l * Dc, O_H, nb); gsync(nb, &s_gen);
        d_gemm3(O_H, p.ew1 + l * DF, 0, 0, O_FF, 0, 0, 1, 512, 2048, 1, 0, sm, nb); gsync(nb, &s_gen);
        d_gemm3(O_FF, p.ew2 + l * DF, 0, 0, O_X, 0, 0, 1, 2048, 512, 2, O_X, sm, nb); gsync(nb, &s_gen);
    }
    d_rmsnorm(O_X, p.elnf, O_HS, nb); gsync(nb, &s_gen);
    for (int l = 0; l < Lc; l++) {
        d_gemm3(O_HS, p.dck + l * DD, p.dcv + l * DD, 0,
                O_ENCK + l * 131072, O_ENCV + l * 131072, 0, 2, 512, 512, 0, 0, sm, nb); gsync(nb, &s_gen);
    }

    for (int i = bid * NT + tid; i < 2048; i += nb * NT) g_s[O_DX + i] = p.emb[i & 511];
    gsync(nb, &s_gen);

    // ===== decode loop (KV-cached) =====
    for (int t = 0; t < Tc; t++) {
        for (int l = 0; l < Lc; l++) {
            d_gemv_ln3(O_DX, p.dln1 + l * Dc, p.dsq + l * DD, p.dsk + l * DD, p.dsv + l * DD,
                       O_DQ, O_SK + l * 32768 + t * 512, O_SV + l * 32768 + t * 512,
                       512, 8192, 8192, 512, 3, 0, sm, nb); gsync(nb, &s_gen);
            d_attn_step(O_DQ, O_SK + l * 32768, O_SV + l * 32768, 8192, t + 1, 0, O_DATTN, sm, nb); gsync(nb, &s_gen);
            d_gemv_res(O_DATTN, p.dso + l * DD, O_DX, 512, 1, sm, nb); gsync(nb, &s_gen);
            d_gemv_ln3(O_DX, p.dln2 + l * Dc, p.dcq + l * DD, 0, 0,
                       O_DQ, 0, 0, 512, 0, 0, 512, 1, 0, sm, nb); gsync(nb, &s_gen);
            d_attn_step(O_DQ, O_ENCK + l * 131072, O_ENCV + l * 131072, 32768, 64, p.mask, O_DATTN, sm, nb); gsync(nb, &s_gen);
            d_gemv_res(O_DATTN, p.dco + l * DD, O_DX, 512, 1, sm, nb); gsync(nb, &s_gen);
            d_gemv_ln3(O_DX, p.dln3 + l * Dc, p.dw1 + l * DF, 0, 0,
                       O_DFF, 0, 0, 2048, 0, 0, 2048, 1, 1, sm, nb); gsync(nb, &s_gen);
            d_gemv_res(O_DFF, p.dw2 + l * DF, O_DX, 2048, 4, sm, nb); gsync(nb, &s_gen);
            d_ppred(4, O_DX, 1, nb); gsync(nb, &s_gen);
        }
        d_gemv_ln3(O_DX, p.dlnf, p.lm, 0, 0, O_LOGITS, 0, 0, Vc, 0, 0, Vc, 1, 0, sm, nb); gsync(nb, &s_gen);
        d_softmax1(sm, nb); gsync(nb, &s_gen);
        d_softmax2(sm, nb); gsync(nb, &s_gen);
        d_softmax3(p.out, t, nb); gsync(nb, &s_gen);
        d_pemb(p.out, p.emb, t, sm, nb); gsync(nb, &s_gen);
        d_ppred(32, O_DX, 0, nb); gsync(nb, &s_gen);
    }
}

// ---- host ----
extern "C" void kernel_launch(void* const* d_in, const int* in_sizes, int n_in,
                              void* d_out, int out_size) {
    (void)in_sizes; (void)n_in; (void)out_size;
    P p;
    p.ids  = (const int*)d_in[0];
    p.mask = (const float*)d_in[1];
    p.emb  = (const float*)d_in[2];
    p.ewq  = (const float*)d_in[3];
    p.ewk  = (const float*)d_in[4];
    p.ewv  = (const float*)d_in[5];
    p.ewo  = (const float*)d_in[6];
    p.eln1 = (const float*)d_in[7];
    p.ew1  = (const float*)d_in[8];
    p.ew2  = (const float*)d_in[9];
    p.eln2 = (const float*)d_in[10];
    p.elnf = (const float*)d_in[11];
    p.dsq  = (const float*)d_in[12];
    p.dsk  = (const float*)d_in[13];
    p.dsv  = (const float*)d_in[14];
    p.dso  = (const float*)d_in[15];
    p.dln1 = (const float*)d_in[16];
    p.dcq  = (const float*)d_in[17];
    p.dck  = (const float*)d_in[18];
    p.dcv  = (const float*)d_in[19];
    p.dco  = (const float*)d_in[20];
    p.dln2 = (const float*)d_in[21];
    p.dw1  = (const float*)d_in[22];
    p.dw2  = (const float*)d_in[23];
    p.dln3 = (const float*)d_in[24];
    p.dlnf = (const float*)d_in[25];
    p.lm   = (const float*)d_in[26];
    p.out  = (float*)d_out;

    int dev = 0;
    cudaGetDevice(&dev);
    int sms = 0;
    cudaDeviceGetAttribute(&sms, cudaDevAttrMultiProcessorCount, dev);
    int bpm = 0;
    cudaOccupancyMaxActiveBlocksPerMultiprocessor(&bpm, k_mega, NT, 0);
    int nb = sms * bpm;
    if (nb > NBMAX) nb = NBMAX;
    if (nb < 1) nb = 1;
    k_mega<<<nb, NT>>>(p, nb);
}